// round 1
// baseline (speedup 1.0000x reference)
#include <cuda_runtime.h>
#include <cuda_bf16.h>

#define NN  100000
#define EE  1600000
#define GG  2048
#define DIN 11
#define DH  128
#define BN_EPS 1e-5f

// ---------------- scratch (device globals; no allocations allowed) ----------
__device__ float d_agg11[NN * DIN];
__device__ float d_h   [NN * DH];
__device__ float d_t   [NN * DH];
__device__ float d_agg [NN * DH];
__device__ float d_pool[GG * DH];
__device__ float d_W1f[DIN * DH];
__device__ float d_b1f[DH];
__device__ float d_W2f[DH * DH];
__device__ float d_b2f[DH];
__device__ float d_W3f[DH * DH];
__device__ float d_b3f[DH];

// ---------------- BN fold: W' = W * (g*rsqrt(v+eps)) per col; b' = (b-m)*s+be
__global__ void fold_kernel(const float* __restrict__ Wa, const float* __restrict__ ba,
                            const float* __restrict__ g,  const float* __restrict__ be,
                            const float* __restrict__ m,  const float* __restrict__ v,
                            int din, float* __restrict__ Wo, float* __restrict__ bo)
{
    int i = blockIdx.x * blockDim.x + threadIdx.x;
    if (i >= din * DH) return;
    int j = i & (DH - 1);
    float sc = g[j] * rsqrtf(v[j] + BN_EPS);
    Wo[i] = Wa[i] * sc;
    if (i < DH) bo[i] = (ba[i] - m[i]) * sc + be[i];
}

// ---------------- layer-1 agg init: agg11 = x (self term) ------------------
__global__ void copy_x_kernel(const float* __restrict__ x)
{
    int i = blockIdx.x * blockDim.x + threadIdx.x;
    if (i < NN * DIN) d_agg11[i] = x[i];
}

// ---------------- layer-1 edge scatter (11 dims, scalar atomics) -----------
__global__ void scatter11_kernel(const float* __restrict__ x,
                                 const int* __restrict__ src, const int* __restrict__ dst)
{
    int e = blockIdx.x * blockDim.x + threadIdx.x;
    if (e >= EE) return;
    int s = src[e], d = dst[e];
    const float* xp = x + s * DIN;
    float* ap = d_agg11 + d * DIN;
#pragma unroll
    for (int k = 0; k < DIN; k++)
        atomicAdd(&ap[k], __ldg(&xp[k]));
}

// ---------------- layer-1 MLP first linear (11 -> 128, BN folded, ReLU) ----
__global__ void mlp1_kernel(float* __restrict__ out, int nrows)
{
    __shared__ float Wf[DIN * DH];
    __shared__ float xs[32][DIN];
    int t = threadIdx.x;   // 128 threads
#pragma unroll
    for (int i = t; i < DIN * DH; i += DH) Wf[i] = d_W1f[i];
    float bj = d_b1f[t];
    int n0 = blockIdx.x * 32;
    int nn = min(32, nrows - n0);
    for (int i = t; i < nn * DIN; i += DH) xs[i / DIN][i % DIN] = d_agg11[n0 * DIN + i];
    __syncthreads();
    for (int n = 0; n < nn; n++) {
        float s = bj;
#pragma unroll
        for (int k = 0; k < DIN; k++) s += xs[n][k] * Wf[k * DH + t];
        out[(n0 + n) * DH + t] = fmaxf(s, 0.f);
    }
}

// ---------------- generic SGEMM: Y = relu(X[nr,128] @ W[128,128] + b) ------
// 128x128 tile per block, 256 threads, 8x8 microtile. Optional dual write.
__global__ __launch_bounds__(256) void gemm128_relu_kernel(
    const float* __restrict__ X, const float* __restrict__ W,
    const float* __restrict__ b, float* __restrict__ Y,
    float* __restrict__ Y2, int nrows)
{
    __shared__ float Xs[16][128];   // [k][row]
    __shared__ float Ws[16][128];   // [k][col]
    int t = threadIdx.x;
    int row0 = blockIdx.x * 128;
    int cx = t & 15;      // col group: cols cx*8 .. cx*8+7
    int cy = t >> 4;      // row group: rows cy*8 .. cy*8+7
    float acc[8][8];
#pragma unroll
    for (int i = 0; i < 8; i++)
#pragma unroll
        for (int j = 0; j < 8; j++) acc[i][j] = 0.f;

    for (int k0 = 0; k0 < DH; k0 += 16) {
        // load X tile (128 rows x 16 k) transposed into Xs[k][row]
#pragma unroll
        for (int i = 0; i < 2; i++) {
            int idx = t + i * 256;          // float4 index 0..511
            int r   = idx >> 2;
            int kk  = (idx & 3) * 4;
            float4 v = make_float4(0.f, 0.f, 0.f, 0.f);
            if (row0 + r < nrows) v = *(const float4*)&X[(row0 + r) * DH + k0 + kk];
            Xs[kk + 0][r] = v.x; Xs[kk + 1][r] = v.y;
            Xs[kk + 2][r] = v.z; Xs[kk + 3][r] = v.w;
        }
        // load W tile (16 k x 128 cols)
#pragma unroll
        for (int i = 0; i < 2; i++) {
            int idx = t + i * 256;
            int kk  = idx >> 5;
            int c   = (idx & 31) * 4;
            *(float4*)&Ws[kk][c] = *(const float4*)&W[(k0 + kk) * DH + c];
        }
        __syncthreads();
#pragma unroll
        for (int kk = 0; kk < 16; kk++) {
            float xr[8], wr[8];
            float4 a0 = *(const float4*)&Xs[kk][cy * 8];
            float4 a1 = *(const float4*)&Xs[kk][cy * 8 + 4];
            float4 b0 = *(const float4*)&Ws[kk][cx * 8];
            float4 b1 = *(const float4*)&Ws[kk][cx * 8 + 4];
            xr[0]=a0.x; xr[1]=a0.y; xr[2]=a0.z; xr[3]=a0.w;
            xr[4]=a1.x; xr[5]=a1.y; xr[6]=a1.z; xr[7]=a1.w;
            wr[0]=b0.x; wr[1]=b0.y; wr[2]=b0.z; wr[3]=b0.w;
            wr[4]=b1.x; wr[5]=b1.y; wr[6]=b1.z; wr[7]=b1.w;
#pragma unroll
            for (int i = 0; i < 8; i++)
#pragma unroll
                for (int j = 0; j < 8; j++)
                    acc[i][j] += xr[i] * wr[j];
        }
        __syncthreads();
    }
    // epilogue: bias + relu, optional dual write
#pragma unroll
    for (int i = 0; i < 8; i++) {
        int r = row0 + cy * 8 + i;
        if (r < nrows) {
#pragma unroll
            for (int j = 0; j < 8; j += 4) {
                int c = cx * 8 + j;
                float4 v;
                v.x = fmaxf(acc[i][j + 0] + b[c + 0], 0.f);
                v.y = fmaxf(acc[i][j + 1] + b[c + 1], 0.f);
                v.z = fmaxf(acc[i][j + 2] + b[c + 2], 0.f);
                v.w = fmaxf(acc[i][j + 3] + b[c + 3], 0.f);
                *(float4*)&Y[r * DH + c] = v;
                if (Y2) *(float4*)&Y2[r * DH + c] = v;
            }
        }
    }
}

// ---------------- 128-dim edge scatter: agg[dst] += h[src] (red.v4) --------
__global__ void scatter128_kernel(const float* __restrict__ h, float* __restrict__ agg,
                                  const int* __restrict__ src, const int* __restrict__ dst)
{
    unsigned idx = blockIdx.x * blockDim.x + threadIdx.x;   // E*32 threads
    unsigned e = idx >> 5;
    if (e >= EE) return;
    int q = (idx & 31) << 2;
    int s = src[e], d = dst[e];
    float4 v = *(const float4*)&h[s * DH + q];
    float* p = &agg[d * DH + q];
    asm volatile("red.global.add.v4.f32 [%0], {%1, %2, %3, %4};"
                 :: "l"(p), "f"(v.x), "f"(v.y), "f"(v.z), "f"(v.w) : "memory");
}

// ---------------- pooling ---------------------------------------------------
__global__ void zero_pool_kernel()
{
    int i = blockIdx.x * blockDim.x + threadIdx.x;
    if (i < GG * DH) d_pool[i] = 0.f;
}

__global__ void pool_kernel(const float* __restrict__ h, const int* __restrict__ batch)
{
    unsigned idx = blockIdx.x * blockDim.x + threadIdx.x;   // N*32 threads
    unsigned i = idx >> 5;
    if (i >= NN) return;
    int q = (idx & 31) << 2;
    int g = batch[i];
    float4 v = *(const float4*)&h[i * DH + q];
    float* p = &d_pool[g * DH + q];
    asm volatile("red.global.add.v4.f32 [%0], {%1, %2, %3, %4};"
                 :: "l"(p), "f"(v.x), "f"(v.y), "f"(v.z), "f"(v.w) : "memory");
}

// ---------------- head: out[g] = relu(pool[g]@lin1+b1) @ lin2 + b2 ---------
__global__ void head_kernel(const float* __restrict__ lin1W, const float* __restrict__ lin1b,
                            const float* __restrict__ lin2W, const float* __restrict__ lin2b,
                            float* __restrict__ out)
{
    __shared__ float xs[DH];
    __shared__ float red[4];
    int g = blockIdx.x, t = threadIdx.x;   // 128 threads
    xs[t] = d_pool[g * DH + t];
    __syncthreads();
    float s = lin1b[t];
#pragma unroll 8
    for (int k = 0; k < DH; k++) s += xs[k] * lin1W[k * DH + t];
    s = fmaxf(s, 0.f) * lin2W[t];
#pragma unroll
    for (int o = 16; o; o >>= 1) s += __shfl_xor_sync(0xffffffffu, s, o);
    if ((t & 31) == 0) red[t >> 5] = s;
    __syncthreads();
    if (t == 0) out[g] = red[0] + red[1] + red[2] + red[3] + lin2b[0];
}

// ---------------- launch ----------------------------------------------------
extern "C" void kernel_launch(void* const* d_in, const int* in_sizes, int n_in,
                              void* d_out, int out_size)
{
    const float* x          = (const float*)d_in[0];
    const int*   edge_index = (const int*)  d_in[1];
    const int*   batch      = (const int*)  d_in[2];
    const float* W1a = (const float*)d_in[3];  const float* b1a = (const float*)d_in[4];
    const float* g1  = (const float*)d_in[5];  const float* be1 = (const float*)d_in[6];
    const float* m1  = (const float*)d_in[7];  const float* v1  = (const float*)d_in[8];
    const float* W1b = (const float*)d_in[9];  const float* b1b = (const float*)d_in[10];
    const float* W2a = (const float*)d_in[11]; const float* b2a = (const float*)d_in[12];
    const float* g2  = (const float*)d_in[13]; const float* be2 = (const float*)d_in[14];
    const float* m2  = (const float*)d_in[15]; const float* v2  = (const float*)d_in[16];
    const float* W2b = (const float*)d_in[17]; const float* b2b = (const float*)d_in[18];
    const float* W3a = (const float*)d_in[19]; const float* b3a = (const float*)d_in[20];
    const float* g3  = (const float*)d_in[21]; const float* be3 = (const float*)d_in[22];
    const float* m3  = (const float*)d_in[23]; const float* v3  = (const float*)d_in[24];
    const float* W3b = (const float*)d_in[25]; const float* b3b = (const float*)d_in[26];
    const float* lin1W = (const float*)d_in[27]; const float* lin1b = (const float*)d_in[28];
    const float* lin2W = (const float*)d_in[29]; const float* lin2b = (const float*)d_in[30];
    float* out = (float*)d_out;

    const int* src = edge_index;
    const int* dst = edge_index + EE;

    // device addresses of scratch symbols
    float *p_h, *p_t, *p_agg, *p_W1f, *p_b1f, *p_W2f, *p_b2f, *p_W3f, *p_b3f;
    cudaGetSymbolAddress((void**)&p_h,   d_h);
    cudaGetSymbolAddress((void**)&p_t,   d_t);
    cudaGetSymbolAddress((void**)&p_agg, d_agg);
    cudaGetSymbolAddress((void**)&p_W1f, d_W1f);
    cudaGetSymbolAddress((void**)&p_b1f, d_b1f);
    cudaGetSymbolAddress((void**)&p_W2f, d_W2f);
    cudaGetSymbolAddress((void**)&p_b2f, d_b2f);
    cudaGetSymbolAddress((void**)&p_W3f, d_W3f);
    cudaGetSymbolAddress((void**)&p_b3f, d_b3f);

    // ---- fold BN into first linear of each MLP
    fold_kernel<<<(DIN * DH + 127) / 128, 128>>>(W1a, b1a, g1, be1, m1, v1, DIN, p_W1f, p_b1f);
    fold_kernel<<<(DH  * DH + 127) / 128, 128>>>(W2a, b2a, g2, be2, m2, v2, DH,  p_W2f, p_b2f);
    fold_kernel<<<(DH  * DH + 127) / 128, 128>>>(W3a, b3a, g3, be3, m3, v3, DH,  p_W3f, p_b3f);

    const int GEMM_BLOCKS = (NN + 127) / 128;

    // ---- layer 1
    copy_x_kernel<<<(NN * DIN + 255) / 256, 256>>>(x);
    scatter11_kernel<<<(EE + 255) / 256, 256>>>(x, src, dst);
    mlp1_kernel<<<(NN + 31) / 32, 128>>>(p_t, NN);
    gemm128_relu_kernel<<<GEMM_BLOCKS, 256>>>(p_t, W1b, b1b, p_h, p_agg, NN);  // h1, agg init

    // ---- layer 2
    scatter128_kernel<<<(EE * 32 + 255) / 256, 256>>>(p_h, p_agg, src, dst);
    gemm128_relu_kernel<<<GEMM_BLOCKS, 256>>>(p_agg, p_W2f, p_b2f, p_t, nullptr, NN);
    gemm128_relu_kernel<<<GEMM_BLOCKS, 256>>>(p_t, W2b, b2b, p_h, p_agg, NN);  // h2, agg init

    // ---- layer 3
    scatter128_kernel<<<(EE * 32 + 255) / 256, 256>>>(p_h, p_agg, src, dst);
    gemm128_relu_kernel<<<GEMM_BLOCKS, 256>>>(p_agg, p_W3f, p_b3f, p_t, nullptr, NN);
    gemm128_relu_kernel<<<GEMM_BLOCKS, 256>>>(p_t, W3b, b3b, p_h, nullptr, NN); // h3

    // ---- pool + head
    zero_pool_kernel<<<(GG * DH + 255) / 256, 256>>>();
    pool_kernel<<<(NN * 32 + 255) / 256, 256>>>(p_h, batch);
    head_kernel<<<GG, 128>>>(lin1W, lin1b, lin2W, lin2b, out);
}

// round 2
// speedup vs baseline: 1.4688x; 1.4688x over previous
#include <cuda_runtime.h>
#include <cuda_bf16.h>

#define NN  100000
#define EE  1600000
#define GG  2048
#define DIN 11
#define DH  128
#define BN_EPS 1e-5f
#define NBLK 98          // ceil(NN/1024)

// ---------------- scratch (device globals; no allocations allowed) ----------
__device__ float d_agg11[NN * DIN];
__device__ float d_h   [NN * DH];
__device__ float d_t   [NN * DH];
__device__ float d_agg [NN * DH];
__device__ float d_pool[GG * DH];
__device__ float d_W1f[DIN * DH];
__device__ float d_b1f[DH];
__device__ float d_W2f[DH * DH];
__device__ float d_b2f[DH];
__device__ float d_W3f[DH * DH];
__device__ float d_b3f[DH];
// CSR scratch
__device__ int d_deg [NN];
__device__ int d_offs[NN];
__device__ int d_cur [NN];
__device__ int d_bsum[NBLK];
__device__ int d_csr [EE];

// ---------------- BN fold: W' = W * (g*rsqrt(v+eps)) per col; b' = (b-m)*s+be
__global__ void fold_kernel(const float* __restrict__ Wa, const float* __restrict__ ba,
                            const float* __restrict__ g,  const float* __restrict__ be,
                            const float* __restrict__ m,  const float* __restrict__ v,
                            int din, float* __restrict__ Wo, float* __restrict__ bo)
{
    int i = blockIdx.x * blockDim.x + threadIdx.x;
    if (i >= din * DH) return;
    int j = i & (DH - 1);
    float sc = g[j] * rsqrtf(v[j] + BN_EPS);
    Wo[i] = Wa[i] * sc;
    if (i < DH) bo[i] = (ba[i] - m[i]) * sc + be[i];
}

// ---------------- CSR build --------------------------------------------------
__global__ void deg_zero_kernel()
{
    int i = blockIdx.x * blockDim.x + threadIdx.x;
    if (i < NN) d_deg[i] = 0;
}

__global__ void deg_count_kernel(const int* __restrict__ dst)
{
    int e = blockIdx.x * blockDim.x + threadIdx.x;
    if (e < EE) atomicAdd(&d_deg[dst[e]], 1);
}

// per-block exclusive scan of deg -> offs(partial), block totals -> bsum
__global__ void scan1_kernel()
{
    __shared__ int wsum[32];
    int i = blockIdx.x * 1024 + threadIdx.x;
    int lane = threadIdx.x & 31, wid = threadIdx.x >> 5;
    int v = (i < NN) ? d_deg[i] : 0;
    int s = v;
#pragma unroll
    for (int o = 1; o < 32; o <<= 1) {
        int t = __shfl_up_sync(0xffffffffu, s, o);
        if (lane >= o) s += t;
    }
    if (lane == 31) wsum[wid] = s;
    __syncthreads();
    if (wid == 0) {
        int ws = (lane < 32) ? wsum[lane] : 0;
#pragma unroll
        for (int o = 1; o < 32; o <<= 1) {
            int t = __shfl_up_sync(0xffffffffu, ws, o);
            if (lane >= o) ws += t;
        }
        wsum[lane] = ws;
    }
    __syncthreads();
    int base = (wid > 0) ? wsum[wid - 1] : 0;
    int incl = base + s;
    if (i < NN) d_offs[i] = incl - v;           // exclusive within block
    if (threadIdx.x == 1023) d_bsum[blockIdx.x] = incl;
}

__global__ void scan2_kernel()
{
    if (threadIdx.x == 0) {
        int run = 0;
        for (int b = 0; b < NBLK; b++) { int t = d_bsum[b]; d_bsum[b] = run; run += t; }
    }
}

__global__ void scan3_kernel()
{
    int i = blockIdx.x * blockDim.x + threadIdx.x;
    if (i >= NN) return;
    int o = d_offs[i] + d_bsum[i >> 10];
    d_offs[i] = o;
    d_cur[i]  = o;
}

__global__ void fill_kernel(const int* __restrict__ src, const int* __restrict__ dst)
{
    int e = blockIdx.x * blockDim.x + threadIdx.x;
    if (e >= EE) return;
    int p = atomicAdd(&d_cur[dst[e]], 1);
    d_csr[p] = src[e];
}

// ---------------- layer-1 aggregation: agg11[i] = x[i] + sum_nbr x[s] -------
__global__ void agg11_kernel(const float* __restrict__ x)
{
    unsigned gt = blockIdx.x * blockDim.x + threadIdx.x;
    unsigned w = gt >> 5;
    if (w >= NN) return;
    int lane = threadIdx.x & 31;
    int start = d_offs[w], len = d_deg[w];
    float acc = (lane < DIN) ? x[w * DIN + lane] : 0.f;
    for (int j = 0; j < len; j++) {
        int s = __ldg(&d_csr[start + j]);
        if (lane < DIN) acc += __ldg(&x[s * DIN + lane]);
    }
    if (lane < DIN) d_agg11[w * DIN + lane] = acc;
}

// ---------------- 128-dim aggregation: agg[i] = h[i] + sum_nbr h[s] --------
__global__ void agg128_kernel(const float* __restrict__ h, float* __restrict__ agg)
{
    unsigned gt = blockIdx.x * blockDim.x + threadIdx.x;
    unsigned w = gt >> 5;
    if (w >= NN) return;
    int lane = threadIdx.x & 31;
    int q = lane << 2;
    int start = d_offs[w], len = d_deg[w];
    float4 acc = *(const float4*)&h[w * DH + q];
    int j = 0;
    for (; j + 2 <= len; j += 2) {
        int s0 = __ldg(&d_csr[start + j]);
        int s1 = __ldg(&d_csr[start + j + 1]);
        float4 v0 = *(const float4*)&h[s0 * DH + q];
        float4 v1 = *(const float4*)&h[s1 * DH + q];
        acc.x += v0.x + v1.x; acc.y += v0.y + v1.y;
        acc.z += v0.z + v1.z; acc.w += v0.w + v1.w;
    }
    if (j < len) {
        int s0 = __ldg(&d_csr[start + j]);
        float4 v0 = *(const float4*)&h[s0 * DH + q];
        acc.x += v0.x; acc.y += v0.y; acc.z += v0.z; acc.w += v0.w;
    }
    *(float4*)&agg[w * DH + q] = acc;
}

// ---------------- layer-1 MLP first linear (11 -> 128, BN folded, ReLU) ----
__global__ void mlp1_kernel(float* __restrict__ out, int nrows)
{
    __shared__ float Wf[DIN * DH];
    __shared__ float xs[32][DIN];
    int t = threadIdx.x;   // 128 threads
#pragma unroll
    for (int i = t; i < DIN * DH; i += DH) Wf[i] = d_W1f[i];
    float bj = d_b1f[t];
    int n0 = blockIdx.x * 32;
    int nn = min(32, nrows - n0);
    for (int i = t; i < nn * DIN; i += DH) xs[i / DIN][i % DIN] = d_agg11[n0 * DIN + i];
    __syncthreads();
    for (int n = 0; n < nn; n++) {
        float s = bj;
#pragma unroll
        for (int k = 0; k < DIN; k++) s += xs[n][k] * Wf[k * DH + t];
        out[(n0 + n) * DH + t] = fmaxf(s, 0.f);
    }
}

// ---------------- generic SGEMM: Y = relu(X[nr,128] @ W[128,128] + b) ------
__global__ __launch_bounds__(256) void gemm128_relu_kernel(
    const float* __restrict__ X, const float* __restrict__ W,
    const float* __restrict__ b, float* __restrict__ Y, int nrows)
{
    __shared__ float Xs[16][128];   // [k][row]
    __shared__ float Ws[16][128];   // [k][col]
    int t = threadIdx.x;
    int row0 = blockIdx.x * 128;
    int cx = t & 15;
    int cy = t >> 4;
    float acc[8][8];
#pragma unroll
    for (int i = 0; i < 8; i++)
#pragma unroll
        for (int j = 0; j < 8; j++) acc[i][j] = 0.f;

    for (int k0 = 0; k0 < DH; k0 += 16) {
#pragma unroll
        for (int i = 0; i < 2; i++) {
            int idx = t + i * 256;
            int r   = idx >> 2;
            int kk  = (idx & 3) * 4;
            float4 v = make_float4(0.f, 0.f, 0.f, 0.f);
            if (row0 + r < nrows) v = *(const float4*)&X[(row0 + r) * DH + k0 + kk];
            Xs[kk + 0][r] = v.x; Xs[kk + 1][r] = v.y;
            Xs[kk + 2][r] = v.z; Xs[kk + 3][r] = v.w;
        }
#pragma unroll
        for (int i = 0; i < 2; i++) {
            int idx = t + i * 256;
            int kk  = idx >> 5;
            int c   = (idx & 31) * 4;
            *(float4*)&Ws[kk][c] = *(const float4*)&W[(k0 + kk) * DH + c];
        }
        __syncthreads();
#pragma unroll
        for (int kk = 0; kk < 16; kk++) {
            float xr[8], wr[8];
            float4 a0 = *(const float4*)&Xs[kk][cy * 8];
            float4 a1 = *(const float4*)&Xs[kk][cy * 8 + 4];
            float4 b0 = *(const float4*)&Ws[kk][cx * 8];
            float4 b1 = *(const float4*)&Ws[kk][cx * 8 + 4];
            xr[0]=a0.x; xr[1]=a0.y; xr[2]=a0.z; xr[3]=a0.w;
            xr[4]=a1.x; xr[5]=a1.y; xr[6]=a1.z; xr[7]=a1.w;
            wr[0]=b0.x; wr[1]=b0.y; wr[2]=b0.z; wr[3]=b0.w;
            wr[4]=b1.x; wr[5]=b1.y; wr[6]=b1.z; wr[7]=b1.w;
#pragma unroll
            for (int i = 0; i < 8; i++)
#pragma unroll
                for (int j = 0; j < 8; j++)
                    acc[i][j] += xr[i] * wr[j];
        }
        __syncthreads();
    }
#pragma unroll
    for (int i = 0; i < 8; i++) {
        int r = row0 + cy * 8 + i;
        if (r < nrows) {
#pragma unroll
            for (int j = 0; j < 8; j += 4) {
                int c = cx * 8 + j;
                float4 v;
                v.x = fmaxf(acc[i][j + 0] + b[c + 0], 0.f);
                v.y = fmaxf(acc[i][j + 1] + b[c + 1], 0.f);
                v.z = fmaxf(acc[i][j + 2] + b[c + 2], 0.f);
                v.w = fmaxf(acc[i][j + 3] + b[c + 3], 0.f);
                *(float4*)&Y[r * DH + c] = v;
            }
        }
    }
}

// ---------------- pooling ---------------------------------------------------
__global__ void zero_pool_kernel()
{
    int i = blockIdx.x * blockDim.x + threadIdx.x;
    if (i < GG * DH) d_pool[i] = 0.f;
}

__global__ void pool_kernel(const float* __restrict__ h, const int* __restrict__ batch)
{
    unsigned idx = blockIdx.x * blockDim.x + threadIdx.x;
    unsigned i = idx >> 5;
    if (i >= NN) return;
    int q = (idx & 31) << 2;
    int g = batch[i];
    float4 v = *(const float4*)&h[i * DH + q];
    float* p = &d_pool[g * DH + q];
    asm volatile("red.global.add.v4.f32 [%0], {%1, %2, %3, %4};"
                 :: "l"(p), "f"(v.x), "f"(v.y), "f"(v.z), "f"(v.w) : "memory");
}

// ---------------- head: out[g] = relu(pool[g]@lin1+b1) @ lin2 + b2 ---------
__global__ void head_kernel(const float* __restrict__ lin1W, const float* __restrict__ lin1b,
                            const float* __restrict__ lin2W, const float* __restrict__ lin2b,
                            float* __restrict__ out)
{
    __shared__ float xs[DH];
    __shared__ float red[4];
    int g = blockIdx.x, t = threadIdx.x;   // 128 threads
    xs[t] = d_pool[g * DH + t];
    __syncthreads();
    float s = lin1b[t];
#pragma unroll 8
    for (int k = 0; k < DH; k++) s += xs[k] * lin1W[k * DH + t];
    s = fmaxf(s, 0.f) * lin2W[t];
#pragma unroll
    for (int o = 16; o; o >>= 1) s += __shfl_xor_sync(0xffffffffu, s, o);
    if ((t & 31) == 0) red[t >> 5] = s;
    __syncthreads();
    if (t == 0) out[g] = red[0] + red[1] + red[2] + red[3] + lin2b[0];
}

// ---------------- launch ----------------------------------------------------
extern "C" void kernel_launch(void* const* d_in, const int* in_sizes, int n_in,
                              void* d_out, int out_size)
{
    const float* x          = (const float*)d_in[0];
    const int*   edge_index = (const int*)  d_in[1];
    const int*   batch      = (const int*)  d_in[2];
    const float* W1a = (const float*)d_in[3];  const float* b1a = (const float*)d_in[4];
    const float* g1  = (const float*)d_in[5];  const float* be1 = (const float*)d_in[6];
    const float* m1  = (const float*)d_in[7];  const float* v1  = (const float*)d_in[8];
    const float* W1b = (const float*)d_in[9];  const float* b1b = (const float*)d_in[10];
    const float* W2a = (const float*)d_in[11]; const float* b2a = (const float*)d_in[12];
    const float* g2  = (const float*)d_in[13]; const float* be2 = (const float*)d_in[14];
    const float* m2  = (const float*)d_in[15]; const float* v2  = (const float*)d_in[16];
    const float* W2b = (const float*)d_in[17]; const float* b2b = (const float*)d_in[18];
    const float* W3a = (const float*)d_in[19]; const float* b3a = (const float*)d_in[20];
    const float* g3  = (const float*)d_in[21]; const float* be3 = (const float*)d_in[22];
    const float* m3  = (const float*)d_in[23]; const float* v3  = (const float*)d_in[24];
    const float* W3b = (const float*)d_in[25]; const float* b3b = (const float*)d_in[26];
    const float* lin1W = (const float*)d_in[27]; const float* lin1b = (const float*)d_in[28];
    const float* lin2W = (const float*)d_in[29]; const float* lin2b = (const float*)d_in[30];
    float* out = (float*)d_out;

    const int* src = edge_index;
    const int* dst = edge_index + EE;

    float *p_h, *p_t, *p_agg, *p_W1f, *p_b1f, *p_W2f, *p_b2f, *p_W3f, *p_b3f;
    cudaGetSymbolAddress((void**)&p_h,   d_h);
    cudaGetSymbolAddress((void**)&p_t,   d_t);
    cudaGetSymbolAddress((void**)&p_agg, d_agg);
    cudaGetSymbolAddress((void**)&p_W1f, d_W1f);
    cudaGetSymbolAddress((void**)&p_b1f, d_b1f);
    cudaGetSymbolAddress((void**)&p_W2f, d_W2f);
    cudaGetSymbolAddress((void**)&p_b2f, d_b2f);
    cudaGetSymbolAddress((void**)&p_W3f, d_W3f);
    cudaGetSymbolAddress((void**)&p_b3f, d_b3f);

    // ---- fold BN into first linear of each MLP
    fold_kernel<<<(DIN * DH + 127) / 128, 128>>>(W1a, b1a, g1, be1, m1, v1, DIN, p_W1f, p_b1f);
    fold_kernel<<<(DH  * DH + 127) / 128, 128>>>(W2a, b2a, g2, be2, m2, v2, DH,  p_W2f, p_b2f);
    fold_kernel<<<(DH  * DH + 127) / 128, 128>>>(W3a, b3a, g3, be3, m3, v3, DH,  p_W3f, p_b3f);

    // ---- CSR build (dst-indexed adjacency)
    deg_zero_kernel<<<(NN + 255) / 256, 256>>>();
    deg_count_kernel<<<(EE + 255) / 256, 256>>>(dst);
    scan1_kernel<<<NBLK, 1024>>>();
    scan2_kernel<<<1, 32>>>();
    scan3_kernel<<<(NN + 255) / 256, 256>>>();
    fill_kernel<<<(EE + 255) / 256, 256>>>(src, dst);

    const int GEMM_BLOCKS = (NN + 127) / 128;
    const int WARP_BLOCKS = (NN * 32 + 255) / 256;

    // ---- layer 1
    agg11_kernel<<<WARP_BLOCKS, 256>>>(x);
    mlp1_kernel<<<(NN + 31) / 32, 128>>>(p_t, NN);
    gemm128_relu_kernel<<<GEMM_BLOCKS, 256>>>(p_t, W1b, b1b, p_h, NN);

    // ---- layer 2
    agg128_kernel<<<WARP_BLOCKS, 256>>>(p_h, p_agg);
    gemm128_relu_kernel<<<GEMM_BLOCKS, 256>>>(p_agg, p_W2f, p_b2f, p_t, NN);
    gemm128_relu_kernel<<<GEMM_BLOCKS, 256>>>(p_t, W2b, b2b, p_h, NN);

    // ---- layer 3
    agg128_kernel<<<WARP_BLOCKS, 256>>>(p_h, p_agg);
    gemm128_relu_kernel<<<GEMM_BLOCKS, 256>>>(p_agg, p_W3f, p_b3f, p_t, NN);
    gemm128_relu_kernel<<<GEMM_BLOCKS, 256>>>(p_t, W3b, b3b, p_h, NN);

    // ---- pool + head
    zero_pool_kernel<<<(GG * DH + 255) / 256, 256>>>();
    pool_kernel<<<(NN * 32 + 255) / 256, 256>>>(p_h, batch);
    head_kernel<<<GG, 128>>>(lin1W, lin1b, lin2W, lin2b, out);
}

// round 3
// speedup vs baseline: 2.2739x; 1.5481x over previous
#include <cuda_runtime.h>
#include <cuda_bf16.h>

#define NN  100000
#define EE  1600000
#define GG  2048
#define DIN 11
#define DH  128
#define BN_EPS 1e-5f
#define NBLK 98          // ceil(NN/1024)

// ---------------- scratch (device globals; no allocations allowed) ----------
__device__ float d_agg11[NN * DIN];
__device__ float d_h   [NN * DH];
__device__ float d_t   [NN * DH];
__device__ float d_agg [NN * DH];
__device__ float d_pool[GG * DH];
__device__ float d_W1f[DIN * DH];
__device__ float d_b1f[DH];
__device__ float d_W2f[DH * DH];
__device__ float d_b2f[DH];
__device__ float d_W3f[DH * DH];
__device__ float d_b3f[DH];
// CSR scratch
__device__ int d_deg [NN];
__device__ int d_offs[NN];
__device__ int d_cur [NN];
__device__ int d_bsum[NBLK];
__device__ int d_csr [EE];

__device__ __forceinline__ unsigned f2tf32(float f)
{
    unsigned u;
    asm("cvt.rna.tf32.f32 %0, %1;" : "=r"(u) : "f"(f));
    return u;
}

// ---------------- BN fold ----------------------------------------------------
__global__ void fold_kernel(const float* __restrict__ Wa, const float* __restrict__ ba,
                            const float* __restrict__ g,  const float* __restrict__ be,
                            const float* __restrict__ m,  const float* __restrict__ v,
                            int din, float* __restrict__ Wo, float* __restrict__ bo)
{
    int i = blockIdx.x * blockDim.x + threadIdx.x;
    if (i >= din * DH) return;
    int j = i & (DH - 1);
    float sc = g[j] * rsqrtf(v[j] + BN_EPS);
    Wo[i] = Wa[i] * sc;
    if (i < DH) bo[i] = (ba[i] - m[i]) * sc + be[i];
}

// ---------------- CSR build --------------------------------------------------
__global__ void deg_zero_kernel()
{
    int i = blockIdx.x * blockDim.x + threadIdx.x;
    if (i < NN) d_deg[i] = 0;
}

__global__ void deg_count_kernel(const int* __restrict__ dst)
{
    int e = blockIdx.x * blockDim.x + threadIdx.x;
    if (e < EE) atomicAdd(&d_deg[dst[e]], 1);
}

__global__ void scan1_kernel()
{
    __shared__ int wsum[32];
    int i = blockIdx.x * 1024 + threadIdx.x;
    int lane = threadIdx.x & 31, wid = threadIdx.x >> 5;
    int v = (i < NN) ? d_deg[i] : 0;
    int s = v;
#pragma unroll
    for (int o = 1; o < 32; o <<= 1) {
        int t = __shfl_up_sync(0xffffffffu, s, o);
        if (lane >= o) s += t;
    }
    if (lane == 31) wsum[wid] = s;
    __syncthreads();
    if (wid == 0) {
        int ws = wsum[lane];
#pragma unroll
        for (int o = 1; o < 32; o <<= 1) {
            int t = __shfl_up_sync(0xffffffffu, ws, o);
            if (lane >= o) ws += t;
        }
        wsum[lane] = ws;
    }
    __syncthreads();
    int base = (wid > 0) ? wsum[wid - 1] : 0;
    int incl = base + s;
    if (i < NN) d_offs[i] = incl - v;
    if (threadIdx.x == 1023) d_bsum[blockIdx.x] = incl;
}

__global__ void scan2_kernel()
{
    if (threadIdx.x == 0) {
        int run = 0;
        for (int b = 0; b < NBLK; b++) { int t = d_bsum[b]; d_bsum[b] = run; run += t; }
    }
}

__global__ void scan3_kernel()
{
    int i = blockIdx.x * blockDim.x + threadIdx.x;
    if (i >= NN) return;
    int o = d_offs[i] + d_bsum[i >> 10];
    d_offs[i] = o;
    d_cur[i]  = o;
}

__global__ void fill_kernel(const int* __restrict__ src, const int* __restrict__ dst)
{
    int e = blockIdx.x * blockDim.x + threadIdx.x;
    if (e >= EE) return;
    int p = atomicAdd(&d_cur[dst[e]], 1);
    d_csr[p] = src[e];
}

// ---------------- layer-1 aggregation ---------------------------------------
__global__ void agg11_kernel(const float* __restrict__ x)
{
    unsigned gt = blockIdx.x * blockDim.x + threadIdx.x;
    unsigned w = gt >> 5;
    if (w >= NN) return;
    int lane = threadIdx.x & 31;
    int start = d_offs[w], len = d_deg[w];
    float acc = (lane < DIN) ? x[w * DIN + lane] : 0.f;
    for (int j = 0; j < len; j++) {
        int s = __ldg(&d_csr[start + j]);
        if (lane < DIN) acc += __ldg(&x[s * DIN + lane]);
    }
    if (lane < DIN) d_agg11[w * DIN + lane] = acc;
}

// ---------------- 128-dim aggregation ---------------------------------------
__global__ void agg128_kernel(const float* __restrict__ h, float* __restrict__ agg)
{
    unsigned gt = blockIdx.x * blockDim.x + threadIdx.x;
    unsigned w = gt >> 5;
    if (w >= NN) return;
    int lane = threadIdx.x & 31;
    int q = lane << 2;
    int start = d_offs[w], len = d_deg[w];
    float4 acc = *(const float4*)&h[w * DH + q];
    int j = 0;
    for (; j + 2 <= len; j += 2) {
        int s0 = __ldg(&d_csr[start + j]);
        int s1 = __ldg(&d_csr[start + j + 1]);
        float4 v0 = *(const float4*)&h[s0 * DH + q];
        float4 v1 = *(const float4*)&h[s1 * DH + q];
        acc.x += v0.x + v1.x; acc.y += v0.y + v1.y;
        acc.z += v0.z + v1.z; acc.w += v0.w + v1.w;
    }
    if (j < len) {
        int s0 = __ldg(&d_csr[start + j]);
        float4 v0 = *(const float4*)&h[s0 * DH + q];
        acc.x += v0.x; acc.y += v0.y; acc.z += v0.z; acc.w += v0.w;
    }
    *(float4*)&agg[w * DH + q] = acc;
}

// ---------------- layer-1 MLP first linear (11 -> 128, BN folded, ReLU) ----
__global__ void mlp1_kernel(float* __restrict__ out, int nrows)
{
    __shared__ float Wf[DIN * DH];
    __shared__ float xs[32][DIN];
    int t = threadIdx.x;   // 128 threads
#pragma unroll
    for (int i = t; i < DIN * DH; i += DH) Wf[i] = d_W1f[i];
    float bj = d_b1f[t];
    int n0 = blockIdx.x * 32;
    int nn = min(32, nrows - n0);
    for (int i = t; i < nn * DIN; i += DH) xs[i / DIN][i % DIN] = d_agg11[n0 * DIN + i];
    __syncthreads();
    for (int n = 0; n < nn; n++) {
        float s = bj;
#pragma unroll
        for (int k = 0; k < DIN; k++) s += xs[n][k] * Wf[k * DH + t];
        out[(n0 + n) * DH + t] = fmaxf(s, 0.f);
    }
}

// ---------------- tf32 tensor-core GEMM: Y = relu(X@W + b) ------------------
// 128x128 block tile, 8 warps (2x4), each warp 64x32 via m16n8k8 tf32 mma.
#define XS_STRIDE 20
#define WS_STRIDE 136
__global__ __launch_bounds__(256) void gemm_tf32_kernel(
    const float* __restrict__ X, const float* __restrict__ W,
    const float* __restrict__ bias, float* __restrict__ Y, int nrows)
{
    __shared__ unsigned Xs[128 * XS_STRIDE];
    __shared__ unsigned Ws[16 * WS_STRIDE];
    int t = threadIdx.x;
    int lane = t & 31, warp = t >> 5;
    int warp_m = warp >> 2;          // 0..1 -> 64 rows each
    int warp_n = warp & 3;           // 0..3 -> 32 cols each
    int row0 = blockIdx.x * 128;
    int lq = lane >> 2;              // lane/4
    int lr = lane & 3;               // lane%4

    float acc[4][4][4];
#pragma unroll
    for (int mt = 0; mt < 4; mt++)
#pragma unroll
        for (int nt = 0; nt < 4; nt++)
#pragma unroll
            for (int i = 0; i < 4; i++) acc[mt][nt][i] = 0.f;

    for (int k0 = 0; k0 < DH; k0 += 16) {
        // stage X tile [128 rows x 16 k] as tf32
#pragma unroll
        for (int i = 0; i < 2; i++) {
            int idx = t + i * 256;          // 0..511 float4 slots
            int r   = idx >> 2;
            int kq  = (idx & 3) * 4;
            float4 v = make_float4(0.f, 0.f, 0.f, 0.f);
            if (row0 + r < nrows) v = *(const float4*)&X[(row0 + r) * DH + k0 + kq];
            Xs[r * XS_STRIDE + kq + 0] = f2tf32(v.x);
            Xs[r * XS_STRIDE + kq + 1] = f2tf32(v.y);
            Xs[r * XS_STRIDE + kq + 2] = f2tf32(v.z);
            Xs[r * XS_STRIDE + kq + 3] = f2tf32(v.w);
        }
        // stage W tile [16 k x 128 n] as tf32
#pragma unroll
        for (int i = 0; i < 2; i++) {
            int idx = t + i * 256;
            int kk  = idx >> 5;
            int c   = (idx & 31) * 4;
            float4 w = *(const float4*)&W[(k0 + kk) * DH + c];
            Ws[kk * WS_STRIDE + c + 0] = f2tf32(w.x);
            Ws[kk * WS_STRIDE + c + 1] = f2tf32(w.y);
            Ws[kk * WS_STRIDE + c + 2] = f2tf32(w.z);
            Ws[kk * WS_STRIDE + c + 3] = f2tf32(w.w);
        }
        __syncthreads();
#pragma unroll
        for (int ks = 0; ks < 16; ks += 8) {
            unsigned bf[4][2];
#pragma unroll
            for (int nt = 0; nt < 4; nt++) {
                int c = warp_n * 32 + nt * 8 + lq;
                bf[nt][0] = Ws[(ks + lr) * WS_STRIDE + c];
                bf[nt][1] = Ws[(ks + 4 + lr) * WS_STRIDE + c];
            }
#pragma unroll
            for (int mt = 0; mt < 4; mt++) {
                int r = warp_m * 64 + mt * 16 + lq;
                int kx = ks + lr;
                unsigned a0 = Xs[r * XS_STRIDE + kx];
                unsigned a1 = Xs[(r + 8) * XS_STRIDE + kx];
                unsigned a2 = Xs[r * XS_STRIDE + kx + 4];
                unsigned a3 = Xs[(r + 8) * XS_STRIDE + kx + 4];
#pragma unroll
                for (int nt = 0; nt < 4; nt++) {
                    asm volatile(
                        "mma.sync.aligned.m16n8k8.row.col.f32.tf32.tf32.f32 "
                        "{%0,%1,%2,%3}, {%4,%5,%6,%7}, {%8,%9}, {%0,%1,%2,%3};"
                        : "+f"(acc[mt][nt][0]), "+f"(acc[mt][nt][1]),
                          "+f"(acc[mt][nt][2]), "+f"(acc[mt][nt][3])
                        : "r"(a0), "r"(a1), "r"(a2), "r"(a3),
                          "r"(bf[nt][0]), "r"(bf[nt][1]));
                }
            }
        }
        __syncthreads();
    }
    // epilogue: bias + relu
#pragma unroll
    for (int nt = 0; nt < 4; nt++) {
        int c = warp_n * 32 + nt * 8 + 2 * lr;
        float b0 = __ldg(&bias[c]);
        float b1 = __ldg(&bias[c + 1]);
#pragma unroll
        for (int mt = 0; mt < 4; mt++) {
            int r = row0 + warp_m * 64 + mt * 16 + lq;
            if (r < nrows) {
                float2 v;
                v.x = fmaxf(acc[mt][nt][0] + b0, 0.f);
                v.y = fmaxf(acc[mt][nt][1] + b1, 0.f);
                *(float2*)&Y[r * DH + c] = v;
            }
            if (r + 8 < nrows) {
                float2 v;
                v.x = fmaxf(acc[mt][nt][2] + b0, 0.f);
                v.y = fmaxf(acc[mt][nt][3] + b1, 0.f);
                *(float2*)&Y[(r + 8) * DH + c] = v;
            }
        }
    }
}

// ---------------- pooling ---------------------------------------------------
__global__ void zero_pool_kernel()
{
    int i = blockIdx.x * blockDim.x + threadIdx.x;
    if (i < GG * DH) d_pool[i] = 0.f;
}

__global__ void pool_kernel(const float* __restrict__ h, const int* __restrict__ batch)
{
    unsigned idx = blockIdx.x * blockDim.x + threadIdx.x;
    unsigned i = idx >> 5;
    if (i >= NN) return;
    int q = (idx & 31) << 2;
    int g = batch[i];
    float4 v = *(const float4*)&h[i * DH + q];
    float* p = &d_pool[g * DH + q];
    asm volatile("red.global.add.v4.f32 [%0], {%1, %2, %3, %4};"
                 :: "l"(p), "f"(v.x), "f"(v.y), "f"(v.z), "f"(v.w) : "memory");
}

// ---------------- head ------------------------------------------------------
__global__ void head_kernel(const float* __restrict__ lin1W, const float* __restrict__ lin1b,
                            const float* __restrict__ lin2W, const float* __restrict__ lin2b,
                            float* __restrict__ out)
{
    __shared__ float xs[DH];
    __shared__ float red[4];
    int g = blockIdx.x, t = threadIdx.x;   // 128 threads
    xs[t] = d_pool[g * DH + t];
    __syncthreads();
    float s = lin1b[t];
#pragma unroll 8
    for (int k = 0; k < DH; k++) s += xs[k] * lin1W[k * DH + t];
    s = fmaxf(s, 0.f) * lin2W[t];
#pragma unroll
    for (int o = 16; o; o >>= 1) s += __shfl_xor_sync(0xffffffffu, s, o);
    if ((t & 31) == 0) red[t >> 5] = s;
    __syncthreads();
    if (t == 0) out[g] = red[0] + red[1] + red[2] + red[3] + lin2b[0];
}

// ---------------- launch ----------------------------------------------------
extern "C" void kernel_launch(void* const* d_in, const int* in_sizes, int n_in,
                              void* d_out, int out_size)
{
    const float* x          = (const float*)d_in[0];
    const int*   edge_index = (const int*)  d_in[1];
    const int*   batch      = (const int*)  d_in[2];
    const float* W1a = (const float*)d_in[3];  const float* b1a = (const float*)d_in[4];
    const float* g1  = (const float*)d_in[5];  const float* be1 = (const float*)d_in[6];
    const float* m1  = (const float*)d_in[7];  const float* v1  = (const float*)d_in[8];
    const float* W1b = (const float*)d_in[9];  const float* b1b = (const float*)d_in[10];
    const float* W2a = (const float*)d_in[11]; const float* b2a = (const float*)d_in[12];
    const float* g2  = (const float*)d_in[13]; const float* be2 = (const float*)d_in[14];
    const float* m2  = (const float*)d_in[15]; const float* v2  = (const float*)d_in[16];
    const float* W2b = (const float*)d_in[17]; const float* b2b = (const float*)d_in[18];
    const float* W3a = (const float*)d_in[19]; const float* b3a = (const float*)d_in[20];
    const float* g3  = (const float*)d_in[21]; const float* be3 = (const float*)d_in[22];
    const float* m3  = (const float*)d_in[23]; const float* v3  = (const float*)d_in[24];
    const float* W3b = (const float*)d_in[25]; const float* b3b = (const float*)d_in[26];
    const float* lin1W = (const float*)d_in[27]; const float* lin1b = (const float*)d_in[28];
    const float* lin2W = (const float*)d_in[29]; const float* lin2b = (const float*)d_in[30];
    float* out = (float*)d_out;

    const int* src = edge_index;
    const int* dst = edge_index + EE;

    float *p_h, *p_t, *p_agg, *p_W1f, *p_b1f, *p_W2f, *p_b2f, *p_W3f, *p_b3f;
    cudaGetSymbolAddress((void**)&p_h,   d_h);
    cudaGetSymbolAddress((void**)&p_t,   d_t);
    cudaGetSymbolAddress((void**)&p_agg, d_agg);
    cudaGetSymbolAddress((void**)&p_W1f, d_W1f);
    cudaGetSymbolAddress((void**)&p_b1f, d_b1f);
    cudaGetSymbolAddress((void**)&p_W2f, d_W2f);
    cudaGetSymbolAddress((void**)&p_b2f, d_b2f);
    cudaGetSymbolAddress((void**)&p_W3f, d_W3f);
    cudaGetSymbolAddress((void**)&p_b3f, d_b3f);

    // ---- fold BN into first linear of each MLP
    fold_kernel<<<(DIN * DH + 127) / 128, 128>>>(W1a, b1a, g1, be1, m1, v1, DIN, p_W1f, p_b1f);
    fold_kernel<<<(DH  * DH + 127) / 128, 128>>>(W2a, b2a, g2, be2, m2, v2, DH,  p_W2f, p_b2f);
    fold_kernel<<<(DH  * DH + 127) / 128, 128>>>(W3a, b3a, g3, be3, m3, v3, DH,  p_W3f, p_b3f);

    // ---- CSR build (dst-indexed adjacency)
    deg_zero_kernel<<<(NN + 255) / 256, 256>>>();
    deg_count_kernel<<<(EE + 255) / 256, 256>>>(dst);
    scan1_kernel<<<NBLK, 1024>>>();
    scan2_kernel<<<1, 32>>>();
    scan3_kernel<<<(NN + 255) / 256, 256>>>();
    fill_kernel<<<(EE + 255) / 256, 256>>>(src, dst);

    const int GEMM_BLOCKS = (NN + 127) / 128;
    const int WARP_BLOCKS = (NN * 32 + 255) / 256;

    // ---- layer 1
    agg11_kernel<<<WARP_BLOCKS, 256>>>(x);
    mlp1_kernel<<<(NN + 31) / 32, 128>>>(p_t, NN);
    gemm_tf32_kernel<<<GEMM_BLOCKS, 256>>>(p_t, W1b, b1b, p_h, NN);

    // ---- layer 2
    agg128_kernel<<<WARP_BLOCKS, 256>>>(p_h, p_agg);
    gemm_tf32_kernel<<<GEMM_BLOCKS, 256>>>(p_agg, p_W2f, p_b2f, p_t, NN);
    gemm_tf32_kernel<<<GEMM_BLOCKS, 256>>>(p_t, W2b, b2b, p_h, NN);

    // ---- layer 3
    agg128_kernel<<<WARP_BLOCKS, 256>>>(p_h, p_agg);
    gemm_tf32_kernel<<<GEMM_BLOCKS, 256>>>(p_agg, p_W3f, p_b3f, p_t, NN);
    gemm_tf32_kernel<<<GEMM_BLOCKS, 256>>>(p_t, W3b, b3b, p_h, NN);

    // ---- pool + head
    zero_pool_kernel<<<(GG * DH + 255) / 256, 256>>>();
    pool_kernel<<<(NN * 32 + 255) / 256, 256>>>(p_h, batch);
    head_kernel<<<GG, 128>>>(lin1W, lin1b, lin2W, lin2b, out);
}

// round 4
// speedup vs baseline: 2.6281x; 1.1558x over previous
#include <cuda_runtime.h>
#include <cuda_fp16.h>

#define NN  100000
#define EE  1600000
#define GG  2048
#define DIN 11
#define DH  128
#define BN_EPS 1e-5f
#define NBLK 98          // ceil(NN/1024)

// ---------------- scratch (device globals; no allocations allowed) ----------
__device__ float  d_agg11[NN * DIN];
__device__ __half d_h   [NN * DH];
__device__ __half d_t   [NN * DH];
__device__ __half d_agg [NN * DH];
__device__ float  d_pool[GG * DH];
__device__ float  d_W1f[DIN * DH];
__device__ float  d_b1f[DH];
__device__ float  d_W2f[DH * DH];
__device__ float  d_b2f[DH];
__device__ float  d_W3f[DH * DH];
__device__ float  d_b3f[DH];
// CSR scratch
__device__ int d_deg [NN];
__device__ int d_offs[NN];
__device__ int d_cur [NN];
__device__ int d_bsum[NBLK];
__device__ int d_csr [EE];

__device__ __forceinline__ unsigned f2tf32(float f)
{
    unsigned u;
    asm("cvt.rna.tf32.f32 %0, %1;" : "=r"(u) : "f"(f));
    return u;
}

// ---------------- BN fold ----------------------------------------------------
__global__ void fold_kernel(const float* __restrict__ Wa, const float* __restrict__ ba,
                            const float* __restrict__ g,  const float* __restrict__ be,
                            const float* __restrict__ m,  const float* __restrict__ v,
                            int din, float* __restrict__ Wo, float* __restrict__ bo)
{
    int i = blockIdx.x * blockDim.x + threadIdx.x;
    if (i >= din * DH) return;
    int j = i & (DH - 1);
    float sc = g[j] * rsqrtf(v[j] + BN_EPS);
    Wo[i] = Wa[i] * sc;
    if (i < DH) bo[i] = (ba[i] - m[i]) * sc + be[i];
}

// ---------------- CSR build --------------------------------------------------
__global__ void deg_zero_kernel()
{
    int i = blockIdx.x * blockDim.x + threadIdx.x;
    if (i < NN) d_deg[i] = 0;
}

__global__ void deg_count_kernel(const int* __restrict__ dst)
{
    int e = blockIdx.x * blockDim.x + threadIdx.x;
    if (e < EE) atomicAdd(&d_deg[dst[e]], 1);
}

__global__ void scan1_kernel()
{
    __shared__ int wsum[32];
    int i = blockIdx.x * 1024 + threadIdx.x;
    int lane = threadIdx.x & 31, wid = threadIdx.x >> 5;
    int v = (i < NN) ? d_deg[i] : 0;
    int s = v;
#pragma unroll
    for (int o = 1; o < 32; o <<= 1) {
        int t = __shfl_up_sync(0xffffffffu, s, o);
        if (lane >= o) s += t;
    }
    if (lane == 31) wsum[wid] = s;
    __syncthreads();
    if (wid == 0) {
        int ws = wsum[lane];
#pragma unroll
        for (int o = 1; o < 32; o <<= 1) {
            int t = __shfl_up_sync(0xffffffffu, ws, o);
            if (lane >= o) ws += t;
        }
        wsum[lane] = ws;
    }
    __syncthreads();
    int base = (wid > 0) ? wsum[wid - 1] : 0;
    int incl = base + s;
    if (i < NN) d_offs[i] = incl - v;
    if (threadIdx.x == 1023) d_bsum[blockIdx.x] = incl;
}

__global__ void scan2_kernel()
{
    if (threadIdx.x == 0) {
        int run = 0;
        for (int b = 0; b < NBLK; b++) { int t = d_bsum[b]; d_bsum[b] = run; run += t; }
    }
}

__global__ void scan3_kernel()
{
    int i = blockIdx.x * blockDim.x + threadIdx.x;
    if (i >= NN) return;
    int o = d_offs[i] + d_bsum[i >> 10];
    d_offs[i] = o;
    d_cur[i]  = o;
}

__global__ void fill_kernel(const int* __restrict__ src, const int* __restrict__ dst)
{
    int e = blockIdx.x * blockDim.x + threadIdx.x;
    if (e >= EE) return;
    int p = atomicAdd(&d_cur[dst[e]], 1);
    d_csr[p] = src[e];
}

// ---------------- layer-1 aggregation ---------------------------------------
__global__ void agg11_kernel(const float* __restrict__ x)
{
    unsigned gt = blockIdx.x * blockDim.x + threadIdx.x;
    unsigned w = gt >> 5;
    if (w >= NN) return;
    int lane = threadIdx.x & 31;
    int start = d_offs[w], len = d_deg[w];
    float acc = (lane < DIN) ? x[w * DIN + lane] : 0.f;
    for (int j = 0; j < len; j++) {
        int s = __ldg(&d_csr[start + j]);
        if (lane < DIN) acc += __ldg(&x[s * DIN + lane]);
    }
    if (lane < DIN) d_agg11[w * DIN + lane] = acc;
}

// ---------------- 128-dim aggregation (fp16 storage, fp32 accumulate) ------
__global__ void agg128_kernel(const __half* __restrict__ h, __half* __restrict__ agg)
{
    unsigned gt = blockIdx.x * blockDim.x + threadIdx.x;
    unsigned w = gt >> 5;
    if (w >= NN) return;
    int lane = threadIdx.x & 31;
    int q = lane << 2;                       // 4 dims per lane
    int start = d_offs[w], len = d_deg[w];
    uint2 raw = *(const uint2*)&h[w * DH + q];
    float2 a0 = __half22float2(*(__half2*)&raw.x);
    float2 a1 = __half22float2(*(__half2*)&raw.y);
    float4 acc = make_float4(a0.x, a0.y, a1.x, a1.y);
    int j = 0;
    for (; j + 2 <= len; j += 2) {
        int s0 = __ldg(&d_csr[start + j]);
        int s1 = __ldg(&d_csr[start + j + 1]);
        uint2 r0 = *(const uint2*)&h[s0 * DH + q];
        uint2 r1 = *(const uint2*)&h[s1 * DH + q];
        float2 v0 = __half22float2(*(__half2*)&r0.x);
        float2 v1 = __half22float2(*(__half2*)&r0.y);
        float2 u0 = __half22float2(*(__half2*)&r1.x);
        float2 u1 = __half22float2(*(__half2*)&r1.y);
        acc.x += v0.x + u0.x; acc.y += v0.y + u0.y;
        acc.z += v1.x + u1.x; acc.w += v1.y + u1.y;
    }
    if (j < len) {
        int s0 = __ldg(&d_csr[start + j]);
        uint2 r0 = *(const uint2*)&h[s0 * DH + q];
        float2 v0 = __half22float2(*(__half2*)&r0.x);
        float2 v1 = __half22float2(*(__half2*)&r0.y);
        acc.x += v0.x; acc.y += v0.y; acc.z += v1.x; acc.w += v1.y;
    }
    uint2 outw;
    *(__half2*)&outw.x = __floats2half2_rn(acc.x, acc.y);
    *(__half2*)&outw.y = __floats2half2_rn(acc.z, acc.w);
    *(uint2*)&agg[w * DH + q] = outw;
}

// ---------------- layer-1 MLP first linear (11 -> 128, BN folded, ReLU) ----
__global__ void mlp1_kernel(__half* __restrict__ out, int nrows)
{
    __shared__ float Wf[DIN * DH];
    __shared__ float xs[32][DIN];
    int t = threadIdx.x;   // 128 threads
#pragma unroll
    for (int i = t; i < DIN * DH; i += DH) Wf[i] = d_W1f[i];
    float bj = d_b1f[t];
    int n0 = blockIdx.x * 32;
    int nn = min(32, nrows - n0);
    for (int i = t; i < nn * DIN; i += DH) xs[i / DIN][i % DIN] = d_agg11[n0 * DIN + i];
    __syncthreads();
    for (int n = 0; n < nn; n++) {
        float s = bj;
#pragma unroll
        for (int k = 0; k < DIN; k++) s += xs[n][k] * Wf[k * DH + t];
        out[(n0 + n) * DH + t] = __float2half(fmaxf(s, 0.f));
    }
}

// ---------------- tf32 tensor-core GEMM: Y = relu(X@W + b), X/Y fp16 -------
#define XS_STRIDE 20
#define WS_STRIDE 136
__global__ __launch_bounds__(256) void gemm_tf32_kernel(
    const __half* __restrict__ X, const float* __restrict__ W,
    const float* __restrict__ bias, __half* __restrict__ Y, int nrows)
{
    __shared__ unsigned Xs[128 * XS_STRIDE];
    __shared__ unsigned Ws[16 * WS_STRIDE];
    int t = threadIdx.x;
    int lane = t & 31, warp = t >> 5;
    int warp_m = warp >> 2;          // 0..1 -> 64 rows each
    int warp_n = warp & 3;           // 0..3 -> 32 cols each
    int row0 = blockIdx.x * 128;
    int lq = lane >> 2;
    int lr = lane & 3;

    float acc[4][4][4];
#pragma unroll
    for (int mt = 0; mt < 4; mt++)
#pragma unroll
        for (int nt = 0; nt < 4; nt++)
#pragma unroll
            for (int i = 0; i < 4; i++) acc[mt][nt][i] = 0.f;

    for (int k0 = 0; k0 < DH; k0 += 16) {
        // stage X tile [128 rows x 16 k]: fp16 global -> tf32 smem (exact)
        {
            int r  = t >> 1;                 // 0..127
            int kh = (t & 1) * 8;            // 0 or 8
            uint4 v = make_uint4(0u, 0u, 0u, 0u);
            if (row0 + r < nrows) v = *(const uint4*)&X[(row0 + r) * DH + k0 + kh];
            float2 f0 = __half22float2(*(__half2*)&v.x);
            float2 f1 = __half22float2(*(__half2*)&v.y);
            float2 f2 = __half22float2(*(__half2*)&v.z);
            float2 f3 = __half22float2(*(__half2*)&v.w);
            unsigned* p = &Xs[r * XS_STRIDE + kh];
            p[0] = f2tf32(f0.x); p[1] = f2tf32(f0.y);
            p[2] = f2tf32(f1.x); p[3] = f2tf32(f1.y);
            p[4] = f2tf32(f2.x); p[5] = f2tf32(f2.y);
            p[6] = f2tf32(f3.x); p[7] = f2tf32(f3.y);
        }
        // stage W tile [16 k x 128 n] fp32 -> tf32
#pragma unroll
        for (int i = 0; i < 2; i++) {
            int idx = t + i * 256;
            int kk  = idx >> 5;
            int c   = (idx & 31) * 4;
            float4 w = *(const float4*)&W[(k0 + kk) * DH + c];
            Ws[kk * WS_STRIDE + c + 0] = f2tf32(w.x);
            Ws[kk * WS_STRIDE + c + 1] = f2tf32(w.y);
            Ws[kk * WS_STRIDE + c + 2] = f2tf32(w.z);
            Ws[kk * WS_STRIDE + c + 3] = f2tf32(w.w);
        }
        __syncthreads();
#pragma unroll
        for (int ks = 0; ks < 16; ks += 8) {
            unsigned bf[4][2];
#pragma unroll
            for (int nt = 0; nt < 4; nt++) {
                int c = warp_n * 32 + nt * 8 + lq;
                bf[nt][0] = Ws[(ks + lr) * WS_STRIDE + c];
                bf[nt][1] = Ws[(ks + 4 + lr) * WS_STRIDE + c];
            }
#pragma unroll
            for (int mt = 0; mt < 4; mt++) {
                int r = warp_m * 64 + mt * 16 + lq;
                int kx = ks + lr;
                unsigned a0 = Xs[r * XS_STRIDE + kx];
                unsigned a1 = Xs[(r + 8) * XS_STRIDE + kx];
                unsigned a2 = Xs[r * XS_STRIDE + kx + 4];
                unsigned a3 = Xs[(r + 8) * XS_STRIDE + kx + 4];
#pragma unroll
                for (int nt = 0; nt < 4; nt++) {
                    asm volatile(
                        "mma.sync.aligned.m16n8k8.row.col.f32.tf32.tf32.f32 "
                        "{%0,%1,%2,%3}, {%4,%5,%6,%7}, {%8,%9}, {%0,%1,%2,%3};"
                        : "+f"(acc[mt][nt][0]), "+f"(acc[mt][nt][1]),
                          "+f"(acc[mt][nt][2]), "+f"(acc[mt][nt][3])
                        : "r"(a0), "r"(a1), "r"(a2), "r"(a3),
                          "r"(bf[nt][0]), "r"(bf[nt][1]));
                }
            }
        }
        __syncthreads();
    }
    // epilogue: bias + relu + fp16 quantize
#pragma unroll
    for (int nt = 0; nt < 4; nt++) {
        int c = warp_n * 32 + nt * 8 + 2 * lr;
        float b0 = __ldg(&bias[c]);
        float b1 = __ldg(&bias[c + 1]);
#pragma unroll
        for (int mt = 0; mt < 4; mt++) {
            int r = row0 + warp_m * 64 + mt * 16 + lq;
            if (r < nrows) {
                __half2 v = __floats2half2_rn(fmaxf(acc[mt][nt][0] + b0, 0.f),
                                              fmaxf(acc[mt][nt][1] + b1, 0.f));
                *(__half2*)&Y[r * DH + c] = v;
            }
            if (r + 8 < nrows) {
                __half2 v = __floats2half2_rn(fmaxf(acc[mt][nt][2] + b0, 0.f),
                                              fmaxf(acc[mt][nt][3] + b1, 0.f));
                *(__half2*)&Y[(r + 8) * DH + c] = v;
            }
        }
    }
}

// ---------------- pooling ---------------------------------------------------
__global__ void zero_pool_kernel()
{
    int i = blockIdx.x * blockDim.x + threadIdx.x;
    if (i < GG * DH) d_pool[i] = 0.f;
}

__global__ void pool_kernel(const __half* __restrict__ h, const int* __restrict__ batch)
{
    unsigned idx = blockIdx.x * blockDim.x + threadIdx.x;
    unsigned i = idx >> 5;
    if (i >= NN) return;
    int q = (idx & 31) << 2;
    int g = batch[i];
    uint2 raw = *(const uint2*)&h[i * DH + q];
    float2 v0 = __half22float2(*(__half2*)&raw.x);
    float2 v1 = __half22float2(*(__half2*)&raw.y);
    float* p = &d_pool[g * DH + q];
    asm volatile("red.global.add.v4.f32 [%0], {%1, %2, %3, %4};"
                 :: "l"(p), "f"(v0.x), "f"(v0.y), "f"(v1.x), "f"(v1.y) : "memory");
}

// ---------------- head ------------------------------------------------------
__global__ void head_kernel(const float* __restrict__ lin1W, const float* __restrict__ lin1b,
                            const float* __restrict__ lin2W, const float* __restrict__ lin2b,
                            float* __restrict__ out)
{
    __shared__ float xs[DH];
    __shared__ float red[4];
    int g = blockIdx.x, t = threadIdx.x;   // 128 threads
    xs[t] = d_pool[g * DH + t];
    __syncthreads();
    float s = lin1b[t];
#pragma unroll 8
    for (int k = 0; k < DH; k++) s += xs[k] * lin1W[k * DH + t];
    s = fmaxf(s, 0.f) * lin2W[t];
#pragma unroll
    for (int o = 16; o; o >>= 1) s += __shfl_xor_sync(0xffffffffu, s, o);
    if ((t & 31) == 0) red[t >> 5] = s;
    __syncthreads();
    if (t == 0) out[g] = red[0] + red[1] + red[2] + red[3] + lin2b[0];
}

// ---------------- launch ----------------------------------------------------
extern "C" void kernel_launch(void* const* d_in, const int* in_sizes, int n_in,
                              void* d_out, int out_size)
{
    const float* x          = (const float*)d_in[0];
    const int*   edge_index = (const int*)  d_in[1];
    const int*   batch      = (const int*)  d_in[2];
    const float* W1a = (const float*)d_in[3];  const float* b1a = (const float*)d_in[4];
    const float* g1  = (const float*)d_in[5];  const float* be1 = (const float*)d_in[6];
    const float* m1  = (const float*)d_in[7];  const float* v1  = (const float*)d_in[8];
    const float* W1b = (const float*)d_in[9];  const float* b1b = (const float*)d_in[10];
    const float* W2a = (const float*)d_in[11]; const float* b2a = (const float*)d_in[12];
    const float* g2  = (const float*)d_in[13]; const float* be2 = (const float*)d_in[14];
    const float* m2  = (const float*)d_in[15]; const float* v2  = (const float*)d_in[16];
    const float* W2b = (const float*)d_in[17]; const float* b2b = (const float*)d_in[18];
    const float* W3a = (const float*)d_in[19]; const float* b3a = (const float*)d_in[20];
    const float* g3  = (const float*)d_in[21]; const float* be3 = (const float*)d_in[22];
    const float* m3  = (const float*)d_in[23]; const float* v3  = (const float*)d_in[24];
    const float* W3b = (const float*)d_in[25]; const float* b3b = (const float*)d_in[26];
    const float* lin1W = (const float*)d_in[27]; const float* lin1b = (const float*)d_in[28];
    const float* lin2W = (const float*)d_in[29]; const float* lin2b = (const float*)d_in[30];
    float* out = (float*)d_out;

    const int* src = edge_index;
    const int* dst = edge_index + EE;

    __half *p_h, *p_t, *p_agg;
    float *p_W1f, *p_b1f, *p_W2f, *p_b2f, *p_W3f, *p_b3f;
    cudaGetSymbolAddress((void**)&p_h,   d_h);
    cudaGetSymbolAddress((void**)&p_t,   d_t);
    cudaGetSymbolAddress((void**)&p_agg, d_agg);
    cudaGetSymbolAddress((void**)&p_W1f, d_W1f);
    cudaGetSymbolAddress((void**)&p_b1f, d_b1f);
    cudaGetSymbolAddress((void**)&p_W2f, d_W2f);
    cudaGetSymbolAddress((void**)&p_b2f, d_b2f);
    cudaGetSymbolAddress((void**)&p_W3f, d_W3f);
    cudaGetSymbolAddress((void**)&p_b3f, d_b3f);

    // ---- fold BN into first linear of each MLP
    fold_kernel<<<(DIN * DH + 127) / 128, 128>>>(W1a, b1a, g1, be1, m1, v1, DIN, p_W1f, p_b1f);
    fold_kernel<<<(DH  * DH + 127) / 128, 128>>>(W2a, b2a, g2, be2, m2, v2, DH,  p_W2f, p_b2f);
    fold_kernel<<<(DH  * DH + 127) / 128, 128>>>(W3a, b3a, g3, be3, m3, v3, DH,  p_W3f, p_b3f);

    // ---- CSR build (dst-indexed adjacency)
    deg_zero_kernel<<<(NN + 255) / 256, 256>>>();
    deg_count_kernel<<<(EE + 255) / 256, 256>>>(dst);
    scan1_kernel<<<NBLK, 1024>>>();
    scan2_kernel<<<1, 32>>>();
    scan3_kernel<<<(NN + 255) / 256, 256>>>();
    fill_kernel<<<(EE + 255) / 256, 256>>>(src, dst);

    const int GEMM_BLOCKS = (NN + 127) / 128;
    const int WARP_BLOCKS = (NN * 32 + 255) / 256;

    // ---- layer 1
    agg11_kernel<<<WARP_BLOCKS, 256>>>(x);
    mlp1_kernel<<<(NN + 31) / 32, 128>>>(p_t, NN);
    gemm_tf32_kernel<<<GEMM_BLOCKS, 256>>>(p_t, W1b, b1b, p_h, NN);

    // ---- layer 2
    agg128_kernel<<<WARP_BLOCKS, 256>>>(p_h, p_agg);
    gemm_tf32_kernel<<<GEMM_BLOCKS, 256>>>(p_agg, p_W2f, p_b2f, p_t, NN);
    gemm_tf32_kernel<<<GEMM_BLOCKS, 256>>>(p_t, W2b, b2b, p_h, NN);

    // ---- layer 3
    agg128_kernel<<<WARP_BLOCKS, 256>>>(p_h, p_agg);
    gemm_tf32_kernel<<<GEMM_BLOCKS, 256>>>(p_agg, p_W3f, p_b3f, p_t, NN);
    gemm_tf32_kernel<<<GEMM_BLOCKS, 256>>>(p_t, W3b, b3b, p_h, NN);

    // ---- pool + head
    zero_pool_kernel<<<(GG * DH + 255) / 256, 256>>>();
    pool_kernel<<<(NN * 32 + 255) / 256, 256>>>(p_h, batch);
    head_kernel<<<GG, 128>>>(lin1W, lin1b, lin2W, lin2b, out);
}

// round 6
// speedup vs baseline: 2.6961x; 1.0259x over previous
#include <cuda_runtime.h>
#include <cuda_fp16.h>

#define NN  100000
#define EE  1600000
#define GG  2048
#define DIN 11
#define DH  128
#define BN_EPS 1e-5f
#define NBLK 98          // ceil(NN/1024)

// ---------------- scratch (device globals; no allocations allowed) ----------
__device__ __half d_h   [NN * DH];
__device__ __half d_t   [NN * DH];
__device__ __half d_agg [NN * DH];
__device__ float  d_pool[GG * DH];
__device__ float  d_W1f[DIN * DH];
__device__ float  d_b1f[DH];
__device__ float  d_W2f[DH * DH];
__device__ float  d_b2f[DH];
__device__ float  d_W3f[DH * DH];
__device__ float  d_b3f[DH];
// CSR scratch
__device__ int d_deg [NN];
__device__ int d_offs[NN];
__device__ int d_cur [NN];
__device__ int d_bsum[NBLK];
__device__ int d_csr [EE];

__device__ __forceinline__ unsigned f2tf32(float f)
{
    unsigned u;
    asm("cvt.rna.tf32.f32 %0, %1;" : "=r"(u) : "f"(f));
    return u;
}

// ---------------- BN fold ----------------------------------------------------
__global__ void fold_kernel(const float* __restrict__ Wa, const float* __restrict__ ba,
                            const float* __restrict__ g,  const float* __restrict__ be,
                            const float* __restrict__ m,  const float* __restrict__ v,
                            int din, float* __restrict__ Wo, float* __restrict__ bo)
{
    int i = blockIdx.x * blockDim.x + threadIdx.x;
    if (i >= din * DH) return;
    int j = i & (DH - 1);
    float sc = g[j] * rsqrtf(v[j] + BN_EPS);
    Wo[i] = Wa[i] * sc;
    if (i < DH) bo[i] = (ba[i] - m[i]) * sc + be[i];
}

// ---------------- CSR build (also zeroes the pool buffer) -------------------
__global__ void deg_zero_kernel()
{
    int i = blockIdx.x * blockDim.x + threadIdx.x;
    if (i < NN) d_deg[i] = 0;
    if (i < GG * DH) d_pool[i] = 0.f;
}

__global__ void deg_count_kernel(const int* __restrict__ dst)
{
    int e = blockIdx.x * blockDim.x + threadIdx.x;
    if (e < EE) atomicAdd(&d_deg[dst[e]], 1);
}

__global__ void scan1_kernel()
{
    __shared__ int wsum[32];
    int i = blockIdx.x * 1024 + threadIdx.x;
    int lane = threadIdx.x & 31, wid = threadIdx.x >> 5;
    int v = (i < NN) ? d_deg[i] : 0;
    int s = v;
#pragma unroll
    for (int o = 1; o < 32; o <<= 1) {
        int t = __shfl_up_sync(0xffffffffu, s, o);
        if (lane >= o) s += t;
    }
    if (lane == 31) wsum[wid] = s;
    __syncthreads();
    if (wid == 0) {
        int ws = wsum[lane];
#pragma unroll
        for (int o = 1; o < 32; o <<= 1) {
            int t = __shfl_up_sync(0xffffffffu, ws, o);
            if (lane >= o) ws += t;
        }
        wsum[lane] = ws;
    }
    __syncthreads();
    int base = (wid > 0) ? wsum[wid - 1] : 0;
    int incl = base + s;
    if (i < NN) d_offs[i] = incl - v;
    if (threadIdx.x == 1023) d_bsum[blockIdx.x] = incl;
}

__global__ void scan2_kernel()
{
    if (threadIdx.x == 0) {
        int run = 0;
        for (int b = 0; b < NBLK; b++) { int t = d_bsum[b]; d_bsum[b] = run; run += t; }
    }
}

__global__ void scan3_kernel()
{
    int i = blockIdx.x * blockDim.x + threadIdx.x;
    if (i >= NN) return;
    int o = d_offs[i] + d_bsum[i >> 10];
    d_offs[i] = o;
    d_cur[i]  = o;
}

__global__ void fill_kernel(const int* __restrict__ src, const int* __restrict__ dst)
{
    int e = blockIdx.x * blockDim.x + threadIdx.x;
    if (e >= EE) return;
    int p = atomicAdd(&d_cur[dst[e]], 1);
    d_csr[p] = src[e];
}

// ---------------- layer 1 fused: agg(11) + first linear + BN + ReLU --------
// One warp per node. Neighbor sum in registers (lanes 0-10), then shfl
// broadcast + smem-resident folded W1 to produce the 128-dim output.
__global__ __launch_bounds__(256) void layer1_kernel(const float* __restrict__ x,
                                                     __half* __restrict__ out)
{
    __shared__ float Wf[DIN * DH];
    __shared__ float bf[DH];
    int t = threadIdx.x;
    for (int i = t; i < DIN * DH; i += 256) Wf[i] = d_W1f[i];
    if (t < DH) bf[t] = d_b1f[t];
    __syncthreads();

    unsigned w = blockIdx.x * 8 + (t >> 5);
    if (w >= NN) return;
    int lane = t & 31;
    int start = d_offs[w], len = d_deg[w];

    float acc = (lane < DIN) ? x[w * DIN + lane] : 0.f;
    int j = 0;
    for (; j + 4 <= len; j += 4) {
        int s0 = __ldg(&d_csr[start + j]);
        int s1 = __ldg(&d_csr[start + j + 1]);
        int s2 = __ldg(&d_csr[start + j + 2]);
        int s3 = __ldg(&d_csr[start + j + 3]);
        if (lane < DIN) {
            acc += __ldg(&x[s0 * DIN + lane]);
            acc += __ldg(&x[s1 * DIN + lane]);
            acc += __ldg(&x[s2 * DIN + lane]);
            acc += __ldg(&x[s3 * DIN + lane]);
        }
    }
    for (; j < len; j++) {
        int s0 = __ldg(&d_csr[start + j]);
        if (lane < DIN) acc += __ldg(&x[s0 * DIN + lane]);
    }

    // out[c] = relu(sum_k acc[k] * Wf[k][c] + bf[c]), lane handles c=lane*4..+3
    int c = lane * 4;
    float s0 = bf[c], s1 = bf[c + 1], s2 = bf[c + 2], s3 = bf[c + 3];
#pragma unroll
    for (int k = 0; k < DIN; k++) {
        float a = __shfl_sync(0xffffffffu, acc, k);
        const float* wr = &Wf[k * DH + c];
        s0 += a * wr[0]; s1 += a * wr[1]; s2 += a * wr[2]; s3 += a * wr[3];
    }
    uint2 ov;
    *(__half2*)&ov.x = __floats2half2_rn(fmaxf(s0, 0.f), fmaxf(s1, 0.f));
    *(__half2*)&ov.y = __floats2half2_rn(fmaxf(s2, 0.f), fmaxf(s3, 0.f));
    *(uint2*)&out[w * DH + c] = ov;
}

// ---------------- 128-dim aggregation (fp16, fp32 accumulate, unroll 4) ----
__global__ void agg128_kernel(const __half* __restrict__ h, __half* __restrict__ agg)
{
    unsigned gt = blockIdx.x * blockDim.x + threadIdx.x;
    unsigned w = gt >> 5;
    if (w >= NN) return;
    int lane = threadIdx.x & 31;
    int q = lane << 2;
    int start = d_offs[w], len = d_deg[w];
    uint2 raw = *(const uint2*)&h[w * DH + q];
    float2 a0 = __half22float2(*(__half2*)&raw.x);
    float2 a1 = __half22float2(*(__half2*)&raw.y);
    float4 acc = make_float4(a0.x, a0.y, a1.x, a1.y);
    int j = 0;
    for (; j + 4 <= len; j += 4) {
        int s0 = __ldg(&d_csr[start + j]);
        int s1 = __ldg(&d_csr[start + j + 1]);
        int s2 = __ldg(&d_csr[start + j + 2]);
        int s3 = __ldg(&d_csr[start + j + 3]);
        uint2 r0 = *(const uint2*)&h[s0 * DH + q];
        uint2 r1 = *(const uint2*)&h[s1 * DH + q];
        uint2 r2 = *(const uint2*)&h[s2 * DH + q];
        uint2 r3 = *(const uint2*)&h[s3 * DH + q];
        float2 p0 = __half22float2(*(__half2*)&r0.x), p1 = __half22float2(*(__half2*)&r0.y);
        float2 q0 = __half22float2(*(__half2*)&r1.x), q1 = __half22float2(*(__half2*)&r1.y);
        float2 u0 = __half22float2(*(__half2*)&r2.x), u1 = __half22float2(*(__half2*)&r2.y);
        float2 t0 = __half22float2(*(__half2*)&r3.x), t1 = __half22float2(*(__half2*)&r3.y);
        acc.x += (p0.x + q0.x) + (u0.x + t0.x);
        acc.y += (p0.y + q0.y) + (u0.y + t0.y);
        acc.z += (p1.x + q1.x) + (u1.x + t1.x);
        acc.w += (p1.y + q1.y) + (u1.y + t1.y);
    }
    for (; j < len; j++) {
        int s0 = __ldg(&d_csr[start + j]);
        uint2 r0 = *(const uint2*)&h[s0 * DH + q];
        float2 p0 = __half22float2(*(__half2*)&r0.x), p1 = __half22float2(*(__half2*)&r0.y);
        acc.x += p0.x; acc.y += p0.y; acc.z += p1.x; acc.w += p1.y;
    }
    uint2 outw;
    *(__half2*)&outw.x = __floats2half2_rn(acc.x, acc.y);
    *(__half2*)&outw.y = __floats2half2_rn(acc.z, acc.w);
    *(uint2*)&agg[w * DH + q] = outw;
}

// ---------------- tf32 tensor-core GEMM: Y = relu(X@W + b), X/Y fp16 -------
// If batch != nullptr: also red-add fp32 result rows into d_pool[batch[r]].
// If Y == nullptr: skip the store (final layer only feeds the pool).
#define XS_STRIDE 20
#define WS_STRIDE 136
__global__ __launch_bounds__(256) void gemm_tf32_kernel(
    const __half* __restrict__ X, const float* __restrict__ W,
    const float* __restrict__ bias, __half* __restrict__ Y,
    const int* __restrict__ batch, int nrows)
{
    __shared__ unsigned Xs[128 * XS_STRIDE];
    __shared__ unsigned Ws[16 * WS_STRIDE];
    int t = threadIdx.x;
    int lane = t & 31, warp = t >> 5;
    int warp_m = warp >> 2;
    int warp_n = warp & 3;
    int row0 = blockIdx.x * 128;
    int lq = lane >> 2;
    int lr = lane & 3;

    float acc[4][4][4];
#pragma unroll
    for (int mt = 0; mt < 4; mt++)
#pragma unroll
        for (int nt = 0; nt < 4; nt++)
#pragma unroll
            for (int i = 0; i < 4; i++) acc[mt][nt][i] = 0.f;

    for (int k0 = 0; k0 < DH; k0 += 16) {
        {
            int r  = t >> 1;
            int kh = (t & 1) * 8;
            uint4 v = make_uint4(0u, 0u, 0u, 0u);
            if (row0 + r < nrows) v = *(const uint4*)&X[(row0 + r) * DH + k0 + kh];
            float2 f0 = __half22float2(*(__half2*)&v.x);
            float2 f1 = __half22float2(*(__half2*)&v.y);
            float2 f2 = __half22float2(*(__half2*)&v.z);
            float2 f3 = __half22float2(*(__half2*)&v.w);
            unsigned* p = &Xs[r * XS_STRIDE + kh];
            p[0] = f2tf32(f0.x); p[1] = f2tf32(f0.y);
            p[2] = f2tf32(f1.x); p[3] = f2tf32(f1.y);
            p[4] = f2tf32(f2.x); p[5] = f2tf32(f2.y);
            p[6] = f2tf32(f3.x); p[7] = f2tf32(f3.y);
        }
#pragma unroll
        for (int i = 0; i < 2; i++) {
            int idx = t + i * 256;
            int kk  = idx >> 5;
            int c   = (idx & 31) * 4;
            float4 w = *(const float4*)&W[(k0 + kk) * DH + c];
            Ws[kk * WS_STRIDE + c + 0] = f2tf32(w.x);
            Ws[kk * WS_STRIDE + c + 1] = f2tf32(w.y);
            Ws[kk * WS_STRIDE + c + 2] = f2tf32(w.z);
            Ws[kk * WS_STRIDE + c + 3] = f2tf32(w.w);
        }
        __syncthreads();
#pragma unroll
        for (int ks = 0; ks < 16; ks += 8) {
            unsigned bf[4][2];
#pragma unroll
            for (int nt = 0; nt < 4; nt++) {
                int c = warp_n * 32 + nt * 8 + lq;
                bf[nt][0] = Ws[(ks + lr) * WS_STRIDE + c];
                bf[nt][1] = Ws[(ks + 4 + lr) * WS_STRIDE + c];
            }
#pragma unroll
            for (int mt = 0; mt < 4; mt++) {
                int r = warp_m * 64 + mt * 16 + lq;
                int kx = ks + lr;
                unsigned a0 = Xs[r * XS_STRIDE + kx];
                unsigned a1 = Xs[(r + 8) * XS_STRIDE + kx];
                unsigned a2 = Xs[r * XS_STRIDE + kx + 4];
                unsigned a3 = Xs[(r + 8) * XS_STRIDE + kx + 4];
#pragma unroll
                for (int nt = 0; nt < 4; nt++) {
                    asm volatile(
                        "mma.sync.aligned.m16n8k8.row.col.f32.tf32.tf32.f32 "
                        "{%0,%1,%2,%3}, {%4,%5,%6,%7}, {%8,%9}, {%0,%1,%2,%3};"
                        : "+f"(acc[mt][nt][0]), "+f"(acc[mt][nt][1]),
                          "+f"(acc[mt][nt][2]), "+f"(acc[mt][nt][3])
                        : "r"(a0), "r"(a1), "r"(a2), "r"(a3),
                          "r"(bf[nt][0]), "r"(bf[nt][1]));
                }
            }
        }
        __syncthreads();
    }
    // epilogue
#pragma unroll
    for (int nt = 0; nt < 4; nt++) {
        int c = warp_n * 32 + nt * 8 + 2 * lr;
        float b0 = __ldg(&bias[c]);
        float b1 = __ldg(&bias[c + 1]);
#pragma unroll
        for (int mt = 0; mt < 4; mt++) {
            int r = row0 + warp_m * 64 + mt * 16 + lq;
            float v0 = fmaxf(acc[mt][nt][0] + b0, 0.f);
            float v1 = fmaxf(acc[mt][nt][1] + b1, 0.f);
            float v2 = fmaxf(acc[mt][nt][2] + b0, 0.f);
            float v3 = fmaxf(acc[mt][nt][3] + b1, 0.f);
            if (r < nrows) {
                if (Y) *(__half2*)&Y[r * DH + c] = __floats2half2_rn(v0, v1);
                if (batch) {
                    int g = __ldg(&batch[r]);
                    float* p = &d_pool[g * DH + c];
                    asm volatile("red.global.add.v2.f32 [%0], {%1, %2};"
                                 :: "l"(p), "f"(v0), "f"(v1) : "memory");
                }
            }
            if (r + 8 < nrows) {
                if (Y) *(__half2*)&Y[(r + 8) * DH + c] = __floats2half2_rn(v2, v3);
                if (batch) {
                    int g = __ldg(&batch[r + 8]);
                    float* p = &d_pool[g * DH + c];
                    asm volatile("red.global.add.v2.f32 [%0], {%1, %2};"
                                 :: "l"(p), "f"(v2), "f"(v3) : "memory");
                }
            }
        }
    }
}

// ---------------- head ------------------------------------------------------
__global__ void head_kernel(const float* __restrict__ lin1W, const float* __restrict__ lin1b,
                            const float* __restrict__ lin2W, const float* __restrict__ lin2b,
                            float* __restrict__ out)
{
    __shared__ float xs[DH];
    __shared__ float red[4];
    int g = blockIdx.x, t = threadIdx.x;   // 128 threads
    xs[t] = d_pool[g * DH + t];
    __syncthreads();
    float s = lin1b[t];
#pragma unroll 8
    for (int k = 0; k < DH; k++) s += xs[k] * lin1W[k * DH + t];
    s = fmaxf(s, 0.f) * lin2W[t];
#pragma unroll
    for (int o = 16; o; o >>= 1) s += __shfl_xor_sync(0xffffffffu, s, o);
    if ((t & 31) == 0) red[t >> 5] = s;
    __syncthreads();
    if (t == 0) out[g] = red[0] + red[1] + red[2] + red[3] + lin2b[0];
}

// ---------------- launch ----------------------------------------------------
extern "C" void kernel_launch(void* const* d_in, const int* in_sizes, int n_in,
                              void* d_out, int out_size)
{
    const float* x          = (const float*)d_in[0];
    const int*   edge_index = (const int*)  d_in[1];
    const int*   batch      = (const int*)  d_in[2];
    const float* W1a = (const float*)d_in[3];  const float* b1a = (const float*)d_in[4];
    const float* g1  = (const float*)d_in[5];  const float* be1 = (const float*)d_in[6];
    const float* m1  = (const float*)d_in[7];  const float* v1  = (const float*)d_in[8];
    const float* W1b = (const float*)d_in[9];  const float* b1b = (const float*)d_in[10];
    const float* W2a = (const float*)d_in[11]; const float* b2a = (const float*)d_in[12];
    const float* g2  = (const float*)d_in[13]; const float* be2 = (const float*)d_in[14];
    const float* m2  = (const float*)d_in[15]; const float* v2  = (const float*)d_in[16];
    const float* W2b = (const float*)d_in[17]; const float* b2b = (const float*)d_in[18];
    const float* W3a = (const float*)d_in[19]; const float* b3a = (const float*)d_in[20];
    const float* g3  = (const float*)d_in[21]; const float* be3 = (const float*)d_in[22];
    const float* m3  = (const float*)d_in[23]; const float* v3  = (const float*)d_in[24];
    const float* W3b = (const float*)d_in[25]; const float* b3b = (const float*)d_in[26];
    const float* lin1W = (const float*)d_in[27]; const float* lin1b = (const float*)d_in[28];
    const float* lin2W = (const float*)d_in[29]; const float* lin2b = (const float*)d_in[30];
    float* out = (float*)d_out;

    const int* src = edge_index;
    const int* dst = edge_index + EE;

    __half *p_h, *p_t, *p_agg;
    float *p_W1f, *p_b1f, *p_W2f, *p_b2f, *p_W3f, *p_b3f;
    cudaGetSymbolAddress((void**)&p_h,   d_h);
    cudaGetSymbolAddress((void**)&p_t,   d_t);
    cudaGetSymbolAddress((void**)&p_agg, d_agg);
    cudaGetSymbolAddress((void**)&p_W1f, d_W1f);
    cudaGetSymbolAddress((void**)&p_b1f, d_b1f);
    cudaGetSymbolAddress((void**)&p_W2f, d_W2f);
    cudaGetSymbolAddress((void**)&p_b2f, d_b2f);
    cudaGetSymbolAddress((void**)&p_W3f, d_W3f);
    cudaGetSymbolAddress((void**)&p_b3f, d_b3f);

    // ---- fold BN into first linear of each MLP
    fold_kernel<<<(DIN * DH + 127) / 128, 128>>>(W1a, b1a, g1, be1, m1, v1, DIN, p_W1f, p_b1f);
    fold_kernel<<<(DH  * DH + 127) / 128, 128>>>(W2a, b2a, g2, be2, m2, v2, DH,  p_W2f, p_b2f);
    fold_kernel<<<(DH  * DH + 127) / 128, 128>>>(W3a, b3a, g3, be3, m3, v3, DH,  p_W3f, p_b3f);

    // ---- CSR build (dst-indexed adjacency) + pool zero
    deg_zero_kernel<<<(GG * DH + 255) / 256, 256>>>();
    deg_count_kernel<<<(EE + 255) / 256, 256>>>(dst);
    scan1_kernel<<<NBLK, 1024>>>();
    scan2_kernel<<<1, 32>>>();
    scan3_kernel<<<(NN + 255) / 256, 256>>>();
    fill_kernel<<<(EE + 255) / 256, 256>>>(src, dst);

    const int GEMM_BLOCKS = (NN + 127) / 128;
    const int WARP_BLOCKS = (NN * 32 + 255) / 256;

    // ---- layer 1 (fused agg + first linear), then second linear
    layer1_kernel<<<(NN + 7) / 8, 256>>>(x, p_t);
    gemm_tf32_kernel<<<GEMM_BLOCKS, 256>>>(p_t, W1b, b1b, p_h, nullptr, NN);

    // ---- layer 2
    agg128_kernel<<<WARP_BLOCKS, 256>>>(p_h, p_agg);
    gemm_tf32_kernel<<<GEMM_BLOCKS, 256>>>(p_agg, p_W2f, p_b2f, p_t, nullptr, NN);
    gemm_tf32_kernel<<<GEMM_BLOCKS, 256>>>(p_t, W2b, b2b, p_h, nullptr, NN);

    // ---- layer 3 (final linear feeds the pool directly, no h3 store)
    agg128_kernel<<<WARP_BLOCKS, 256>>>(p_h, p_agg);
    gemm_tf32_kernel<<<GEMM_BLOCKS, 256>>>(p_agg, p_W3f, p_b3f, p_t, nullptr, NN);
    gemm_tf32_kernel<<<GEMM_BLOCKS, 256>>>(p_t, W3b, b3b, nullptr, batch, NN);

    // ---- head
    head_kernel<<<GG, 128>>>(lin1W, lin1b, lin2W, lin2b, out);
}